// round 15
// baseline (speedup 1.0000x reference)
#include <cuda_runtime.h>
#include <cuda_fp16.h>
#include <cstdint>

// ---------------------------------------------------------------------------
// y = EqualizedConv2d(stride=2, 3x3, 256->512, 1/48)( blur4x4(x) ) + bias
// Round 14: fp16 m16n8k16 GEMM, warp tile 64x64 (CTA 128x128, 128 thr,
// 2 CTAs/SM), A fragments as LDG.64 from channel-pair-interleaved phase-pair
// planes. No smem / no syncs in mainloop.  Blur emits whole uint32 half-pairs.
//   M=65536, N=512, K=2304 = 144 k16-chunks (128 main + 16 tail).
// ---------------------------------------------------------------------------

#define NIMG   16
#define CIN    256
#define HIN    128
#define COUT   512
#define KDIM   2304
#define MDIM   65536
#define XPW    66                  // plane row pitch in positions (65 valid)
#define CPOS   4290                // 65*66 positions per (n, channel-pair)
#define IMGSTR (128 * CPOS)        // uint2 elements per image (128 ch-pairs)
#define NKC    144                 // k16 chunks (128 main + 16 tail)

// Planes: entry = uint2 { phasepair(ch 2cp), phasepair(ch 2cp+1) }
//  P01[pos] halves = { xb(2y,2x),   xb(2y,2x+1) }
//  P23[pos] halves = { xb(2y+1,2x), xb(2y+1,2x+1) }
//  P02[pos] halves = { xb(2y,2x),   xb(2y+1,2x) }
__device__ uint2 g_P01v[(size_t)NIMG * IMGSTR];
__device__ uint2 g_P23v[(size_t)NIMG * IMGSTR];
__device__ uint2 g_P02v[(size_t)NIMG * IMGSTR];
__device__ uint4 g_Bq4[4 * NKC * 8 * 32];      // 2.36 MB fragment table
__device__ float g_k[4];                       // separable 1-D taps

// tap order within a channel: sigma = [0,1,3,4,6,7,2,5]
__device__ __constant__ int c_sigma[8] = {0, 1, 3, 4, 6, 7, 2, 5};

// ---------------------------------------------------------------------------
// Kernel 0: 1-D taps (row sums of normalized outer-product kernel; exact)
// ---------------------------------------------------------------------------
__global__ void prep_k_kernel(const float* __restrict__ bk) {
    if (threadIdx.x < 4) {
        int t = threadIdx.x;
        g_k[t] = bk[t*4+0] + bk[t*4+1] + bk[t*4+2] + bk[t*4+3];
    }
}

// ---------------------------------------------------------------------------
// Kernel 1: fused separable blur -> quad outputs -> three 32-bit pair stores.
// CTA = (nc, quad-row quarter {17,16,16,16}).
// ---------------------------------------------------------------------------
__global__ void __launch_bounds__(256) blur_kernel(const float* __restrict__ x) {
    __shared__ float xs[35 * 128];
    __shared__ float hs[35 * 132];

    const int nc  = blockIdx.x;
    const int q   = blockIdx.y;
    const int tid = threadIdx.x;

    const int y0   = (q == 0) ? 0 : 17 + (q - 1) * 16;   // first quad row
    const int ycnt = (q == 0) ? 17 : 16;

    // input rows needed: [2*y0-2, min(2*y0+2*ycnt-1,128)+1] ∩ [0,127]
    int in_lo = 2 * y0 - 2;                   if (in_lo < 0)   in_lo = 0;
    int in_hi = 2 * y0 + 2 * ycnt + 1;        if (in_hi > 128) in_hi = 128;
    const int nrows = in_hi - in_lo;          // <= 35

    const float k0 = g_k[0], k1 = g_k[1], k2 = g_k[2], k3 = g_k[3];

    {
        const float4* src = (const float4*)(x + ((size_t)nc * HIN + in_lo) * HIN);
        float4* dst = (float4*)xs;
        for (int t = tid; t < nrows * 32; t += 256) dst[t] = src[t];
    }
    __syncthreads();

    for (int t = tid; t < nrows * 129; t += 256) {
        int j = t % 129, rr = t / 129;
        const float* xr = xs + rr * 128;
        float acc = 0.f;
        int c = j - 2;
        if ((unsigned)(c    ) < 128u) acc += k0 * xr[c];
        if ((unsigned)(c + 1) < 128u) acc += k1 * xr[c + 1];
        if ((unsigned)(c + 2) < 128u) acc += k2 * xr[c + 2];
        if ((unsigned)(c + 3) < 128u) acc += k3 * xr[c + 3];
        hs[rr * 132 + j] = acc;
    }
    __syncthreads();

    const int n   = nc >> 8;            // image
    const int ch  = nc & 255;           // channel
    const int cpg = n * 128 + (ch >> 1);
    const int sub = ch & 1;
    unsigned* P01 = (unsigned*)g_P01v;
    unsigned* P23 = (unsigned*)g_P23v;
    unsigned* P02 = (unsigned*)g_P02v;

    for (int t = tid; t < ycnt * 65; t += 256) {
        int xq = t % 65;
        int yq = t / 65 + y0;

        // vertical conv at output rows 2yq (+1) and cols 2xq (+1)
        float v[2][2];
#pragma unroll
        for (int dy = 0; dy < 2; ++dy) {
            int i = 2 * yq + dy;
#pragma unroll
            for (int dx = 0; dx < 2; ++dx) v[dy][dx] = 0.f;
            if (i <= 128) {
                int r = i - 2;
                float a0 = 0.f, a1 = 0.f;
#pragma unroll
                for (int u = 0; u < 4; ++u) {
                    int rr = r + u;
                    if ((unsigned)rr < 128u) {
                        const float* hr = hs + (rr - in_lo) * 132 + 2 * xq;
                        float kk = (u == 0) ? k0 : (u == 1) ? k1 : (u == 2) ? k2 : k3;
                        a0 += kk * hr[0];
                        a1 += kk * hr[1];   // col 2xq+1 <= 129? hs has 129 cols (0..128);
                                            // at xq=64: 2xq+1=129 -> reads hs col 129 pad
                    }
                }
                v[dy][0] = a0;
                v[dy][1] = a1;
            }
        }
        // NOTE: at xq==64 the dx=1 value is garbage but never read by the GEMM;
        // hs row stride 132 > 129 so the read stays in-bounds.

        __half2 h01 = __halves2half2(__float2half_rn(v[0][0]), __float2half_rn(v[0][1]));
        __half2 h23 = __halves2half2(__float2half_rn(v[1][0]), __float2half_rn(v[1][1]));
        __half2 h02 = __halves2half2(__float2half_rn(v[0][0]), __float2half_rn(v[1][0]));

        size_t e = ((size_t)cpg * CPOS + yq * XPW + xq) * 2 + sub;
        P01[e] = *(unsigned*)&h01;
        P23[e] = *(unsigned*)&h23;
        P02[e] = *(unsigned*)&h02;
    }
}

// ---------------------------------------------------------------------------
// Kernel 2: B fragment table (fp16, scaled) — identical convention to R13.
// ---------------------------------------------------------------------------
__global__ void bprep_kernel(const float* __restrict__ w) {
    int idx = blockIdx.x * 256 + threadIdx.x;      // < 147456
    if (idx >= 4 * NKC * 8 * 32) return;
    int lane = idx & 31;
    int qp   = (idx >> 5) & 7;
    int rest = idx >> 8;
    int kc   = rest % NKC;
    int nt   = rest / NKC;
    int g  = lane >> 2;
    int tg = lane & 3;
    const float s = 1.0f / 48.0f;

    unsigned r[4];
#pragma unroll
    for (int h = 0; h < 2; ++h) {
        int ni = 2 * qp + h;
        int n  = nt * 128 + ni * 8 + g;
        const float* wn_ = w + (size_t)n * KDIM;   // [c][tap] natural order
        float b0x, b0y, b1x, b1y;
        if (kc < 128) {
            int c0 = 2 * kc, c1 = c0 + 1;
            int t0 = c_sigma[2 * tg], t1 = c_sigma[2 * tg + 1];
            b0x = wn_[c0 * 9 + t0] * s;  b0y = wn_[c0 * 9 + t1] * s;
            b1x = wn_[c1 * 9 + t0] * s;  b1y = wn_[c1 * 9 + t1] * s;
        } else {
            int tb = (kc - 128) * 16;
            b0x = wn_[(tb + 2 * tg)     * 9 + 8] * s;
            b0y = wn_[(tb + 2 * tg + 1) * 9 + 8] * s;
            b1x = wn_[(tb + 8 + 2 * tg)     * 9 + 8] * s;
            b1y = wn_[(tb + 8 + 2 * tg + 1) * 9 + 8] * s;
        }
        __half2 h0 = __halves2half2(__float2half_rn(b0x), __float2half_rn(b0y));
        __half2 h1 = __halves2half2(__float2half_rn(b1x), __float2half_rn(b1y));
        r[2 * h]     = *(unsigned*)&h0;
        r[2 * h + 1] = *(unsigned*)&h1;
    }
    g_Bq4[idx] = make_uint4(r[0], r[1], r[2], r[3]);
}

// ---------------------------------------------------------------------------
// Kernel 3: fp16 GEMM. CTA 128x128, 4 warps (warpm = w&1, wn = w>>1),
// warp tile 64x64. A: 8 LDG.64 / warp / chunk. B: 4 LDG.128.
// ---------------------------------------------------------------------------
#define MMA_F16(acc, a, b0, b1)                                                \
    asm volatile(                                                              \
        "mma.sync.aligned.m16n8k16.row.col.f32.f16.f16.f32 "                   \
        "{%0,%1,%2,%3}, {%4,%5,%6,%7}, {%8,%9}, {%0,%1,%2,%3};\n"              \
        : "+f"((acc)[0]), "+f"((acc)[1]), "+f"((acc)[2]), "+f"((acc)[3])       \
        : "r"((a)[0]), "r"((a)[1]), "r"((a)[2]), "r"((a)[3]),                  \
          "r"(b0), "r"(b1))

__global__ void __launch_bounds__(128, 2)
gemm_kernel(const float* __restrict__ bias, float* __restrict__ out) {
    const int tid   = threadIdx.x;
    const int warp  = tid >> 5;
    const int lane  = tid & 31;
    const int g     = lane >> 2;
    const int tg    = lane & 3;
    const int warpm = warp & 1;
    const int wn    = warp >> 1;
    const int nt    = blockIdx.x;
    const int m0    = blockIdx.y << 7;

    // lane-constant plane + position offset
    const uint2* pA = (tg == 1) ? g_P23v : (tg == 3) ? g_P02v : g_P01v;
    const int roff  = (tg == 2) ? XPW : (tg == 3) ? 1 : 0;

    int abase[4], tbase[4];
#pragma unroll
    for (int mi = 0; mi < 4; ++mi) {
        int m  = m0 + warpm * 64 + mi * 16 + g;
        int bb = (m >> 12) * IMGSTR + ((m >> 6) & 63) * XPW + (m & 63);
        abase[mi] = bb + roff;
        tbase[mi] = bb + XPW + 1;       // tap-8 position (y+1, x+1)
    }

    const uint4* Bt = g_Bq4 + (size_t)(nt * NKC) * 256 + wn * 128 + lane;

    float acc[4][8][4];
#pragma unroll
    for (int a = 0; a < 4; ++a)
#pragma unroll
        for (int b = 0; b < 8; ++b)
#pragma unroll
            for (int c = 0; c < 4; ++c) acc[a][b][c] = 0.f;

    unsigned aF[2][4][4];
    uint4    bF[2][4];

#define LOAD_MAIN(KC, S)                                                       \
    {                                                                          \
        const int co_ = (KC) * CPOS;                                           \
        _Pragma("unroll")                                                      \
        for (int mi = 0; mi < 4; ++mi) {                                       \
            uint2 u_ = pA[abase[mi] + co_];                                    \
            uint2 v_ = pA[abase[mi] + co_ + 8];                                \
            aF[S][mi][0] = u_.x;  aF[S][mi][2] = u_.y;                         \
            aF[S][mi][1] = v_.x;  aF[S][mi][3] = v_.y;                         \
        }                                                                      \
        const uint4* bp_ = Bt + (size_t)(KC) * 256;                            \
        _Pragma("unroll")                                                      \
        for (int np = 0; np < 4; ++np) bF[S][np] = bp_[np * 32];               \
    }

#define LOAD_TAIL(T, S)                                                        \
    {                                                                          \
        const int c0_ = ((T) * 8 + tg) * CPOS;                                 \
        const int c1_ = c0_ + 4 * CPOS;                                        \
        _Pragma("unroll")                                                      \
        for (int mi = 0; mi < 4; ++mi) {                                       \
            int b_ = tbase[mi];                                                \
            uint2 u_;                                                          \
            u_ = g_P01v[b_ + c0_];     aF[S][mi][0] = __byte_perm(u_.x, u_.y, 0x5410); \
            u_ = g_P01v[b_ + c0_ + 8]; aF[S][mi][1] = __byte_perm(u_.x, u_.y, 0x5410); \
            u_ = g_P01v[b_ + c1_];     aF[S][mi][2] = __byte_perm(u_.x, u_.y, 0x5410); \
            u_ = g_P01v[b_ + c1_ + 8]; aF[S][mi][3] = __byte_perm(u_.x, u_.y, 0x5410); \
        }                                                                      \
        const uint4* bp_ = Bt + (size_t)(128 + (T)) * 256;                     \
        _Pragma("unroll")                                                      \
        for (int np = 0; np < 4; ++np) bF[S][np] = bp_[np * 32];               \
    }

#define DO_MMAS(S)                                                             \
    _Pragma("unroll")                                                          \
    for (int np = 0; np < 4; ++np) {                                           \
        _Pragma("unroll")                                                      \
        for (int mi = 0; mi < 4; ++mi) {                                       \
            MMA_F16(acc[mi][2 * np],     aF[S][mi], bF[S][np].x, bF[S][np].y); \
            MMA_F16(acc[mi][2 * np + 1], aF[S][mi], bF[S][np].z, bF[S][np].w); \
        }                                                                      \
    }

    LOAD_MAIN(0, 0);

#pragma unroll 2
    for (int kc = 0; kc < 128; ++kc) {
        const int s = kc & 1;
        if (kc < 127) { LOAD_MAIN(kc + 1, s ^ 1); }
        else          { LOAD_TAIL(0, s ^ 1); }
        DO_MMAS(s);
    }
#pragma unroll 2
    for (int t = 0; t < 16; ++t) {
        const int s = (128 + t) & 1;
        if (t < 15) LOAD_TAIL(t + 1, s ^ 1);
        DO_MMAS(s);
    }
#undef LOAD_MAIN
#undef LOAD_TAIL
#undef DO_MMAS

    // epilogue: D[m][oc] -> out[n, oc, oh, ow] + bias
#pragma unroll
    for (int mi = 0; mi < 4; ++mi) {
        int m   = m0 + warpm * 64 + mi * 16 + g;
        int n16 = m >> 12;
        int rem = m & 4095;
#pragma unroll
        for (int ni = 0; ni < 8; ++ni) {
            int oc = nt * 128 + wn * 64 + ni * 8 + tg * 2;
            float bv0 = __ldg(&bias[oc]);
            float bv1 = __ldg(&bias[oc + 1]);
            float* p = out + (((size_t)(n16 * COUT + oc)) << 12) + rem;
            p[0]    = acc[mi][ni][0] + bv0;   // (m,   oc)
            p[4096] = acc[mi][ni][1] + bv1;   // (m,   oc+1)
            p[8]    = acc[mi][ni][2] + bv0;   // (m+8, oc)
            p[4104] = acc[mi][ni][3] + bv1;   // (m+8, oc+1)
        }
    }
}

// ---------------------------------------------------------------------------
extern "C" void kernel_launch(void* const* d_in, const int* in_sizes, int n_in,
                              void* d_out, int out_size) {
    const float* x    = (const float*)d_in[0];
    const float* w    = (const float*)d_in[1];
    const float* bias = (const float*)d_in[2];
    const float* bk   = (const float*)d_in[3];
    float* out = (float*)d_out;
    (void)in_sizes; (void)n_in; (void)out_size;

    prep_k_kernel<<<1, 32>>>(bk);

    blur_kernel<<<dim3(NIMG * CIN, 4), 256>>>(x);

    bprep_kernel<<<(4 * NKC * 8 * 32 + 255) / 256, 256>>>(w);

    dim3 grid(COUT / 128, MDIM / 128);      // (4, 512): n fast -> A L2 reuse
    gemm_kernel<<<grid, 128>>>(bias, out);
}

// round 16
// speedup vs baseline: 1.0535x; 1.0535x over previous
#include <cuda_runtime.h>
#include <cuda_fp16.h>
#include <cstdint>

// ---------------------------------------------------------------------------
// y = EqualizedConv2d(stride=2, 3x3, 256->512, 1/48)( blur4x4(x) ) + bias
// Round 16: R13's proven 16-warp fp16 GEMM skeleton (warp 32x64, 2 CTA/SM)
// + R14's channel-pair uint2 planes: each A fragment pair = ONE LDG.64.
// 8 LDG / warp-chunk (was 12). No smem, no mainloop syncs.
//   M=65536, N=512, K=2304 = 144 k16-chunks (128 main + 16 tail).
// ---------------------------------------------------------------------------

#define NIMG   16
#define CIN    256
#define HIN    128
#define COUT   512
#define KDIM   2304
#define MDIM   65536
#define XPW    66                  // plane row pitch in positions (65 valid)
#define CPOS   4290                // 65*66 positions per (n, channel-pair)
#define IMGSTR (128 * CPOS)        // uint2 elements per image (128 ch-pairs)
#define NKC    144                 // k16 chunks (128 main + 16 tail)

// Planes: entry = uint2 { phasepair(ch 2cp), phasepair(ch 2cp+1) }
//  P01[pos] halves = { xb(2y,2x),   xb(2y,2x+1) }
//  P23[pos] halves = { xb(2y+1,2x), xb(2y+1,2x+1) }
//  P02[pos] halves = { xb(2y,2x),   xb(2y+1,2x) }
__device__ uint2 g_P01v[(size_t)NIMG * IMGSTR];
__device__ uint2 g_P23v[(size_t)NIMG * IMGSTR];
__device__ uint2 g_P02v[(size_t)NIMG * IMGSTR];
__device__ uint4 g_Bq4[4 * NKC * 8 * 32];      // 2.36 MB fragment table
__device__ float g_k[4];                       // separable 1-D taps

// tap order within a channel: sigma = [0,1,3,4,6,7,2,5]
__device__ __constant__ int c_sigma[8] = {0, 1, 3, 4, 6, 7, 2, 5};

// ---------------------------------------------------------------------------
// Kernel 0: 1-D taps (row sums of normalized outer-product kernel; exact)
// ---------------------------------------------------------------------------
__global__ void prep_k_kernel(const float* __restrict__ bk) {
    if (threadIdx.x < 4) {
        int t = threadIdx.x;
        g_k[t] = bk[t*4+0] + bk[t*4+1] + bk[t*4+2] + bk[t*4+3];
    }
}

// ---------------------------------------------------------------------------
// Kernel 1: fused separable blur -> quad outputs -> three 32-bit pair stores.
// (verified in R14/R15: rel_err unchanged)
// ---------------------------------------------------------------------------
__global__ void __launch_bounds__(256) blur_kernel(const float* __restrict__ x) {
    __shared__ float xs[35 * 128];
    __shared__ float hs[35 * 132];

    const int nc  = blockIdx.x;
    const int q   = blockIdx.y;
    const int tid = threadIdx.x;

    const int y0   = (q == 0) ? 0 : 17 + (q - 1) * 16;
    const int ycnt = (q == 0) ? 17 : 16;

    int in_lo = 2 * y0 - 2;                   if (in_lo < 0)   in_lo = 0;
    int in_hi = 2 * y0 + 2 * ycnt + 1;        if (in_hi > 128) in_hi = 128;
    const int nrows = in_hi - in_lo;          // <= 35

    const float k0 = g_k[0], k1 = g_k[1], k2 = g_k[2], k3 = g_k[3];

    {
        const float4* src = (const float4*)(x + ((size_t)nc * HIN + in_lo) * HIN);
        float4* dst = (float4*)xs;
        for (int t = tid; t < nrows * 32; t += 256) dst[t] = src[t];
    }
    __syncthreads();

    for (int t = tid; t < nrows * 129; t += 256) {
        int j = t % 129, rr = t / 129;
        const float* xr = xs + rr * 128;
        float acc = 0.f;
        int c = j - 2;
        if ((unsigned)(c    ) < 128u) acc += k0 * xr[c];
        if ((unsigned)(c + 1) < 128u) acc += k1 * xr[c + 1];
        if ((unsigned)(c + 2) < 128u) acc += k2 * xr[c + 2];
        if ((unsigned)(c + 3) < 128u) acc += k3 * xr[c + 3];
        hs[rr * 132 + j] = acc;
    }
    __syncthreads();

    const int n   = nc >> 8;
    const int ch  = nc & 255;
    const int cpg = n * 128 + (ch >> 1);
    const int sub = ch & 1;
    unsigned* P01 = (unsigned*)g_P01v;
    unsigned* P23 = (unsigned*)g_P23v;
    unsigned* P02 = (unsigned*)g_P02v;

    for (int t = tid; t < ycnt * 65; t += 256) {
        int xq = t % 65;
        int yq = t / 65 + y0;

        float v[2][2];
#pragma unroll
        for (int dy = 0; dy < 2; ++dy) {
            int i = 2 * yq + dy;
#pragma unroll
            for (int dx = 0; dx < 2; ++dx) v[dy][dx] = 0.f;
            if (i <= 128) {
                int r = i - 2;
                float a0 = 0.f, a1 = 0.f;
#pragma unroll
                for (int u = 0; u < 4; ++u) {
                    int rr = r + u;
                    if ((unsigned)rr < 128u) {
                        const float* hr = hs + (rr - in_lo) * 132 + 2 * xq;
                        float kk = (u == 0) ? k0 : (u == 1) ? k1 : (u == 2) ? k2 : k3;
                        a0 += kk * hr[0];
                        a1 += kk * hr[1];   // xq==64: dx=1 garbage, never read
                    }
                }
                v[dy][0] = a0;
                v[dy][1] = a1;
            }
        }

        __half2 h01 = __halves2half2(__float2half_rn(v[0][0]), __float2half_rn(v[0][1]));
        __half2 h23 = __halves2half2(__float2half_rn(v[1][0]), __float2half_rn(v[1][1]));
        __half2 h02 = __halves2half2(__float2half_rn(v[0][0]), __float2half_rn(v[1][0]));

        size_t e = ((size_t)cpg * CPOS + yq * XPW + xq) * 2 + sub;
        P01[e] = *(unsigned*)&h01;
        P23[e] = *(unsigned*)&h23;
        P02[e] = *(unsigned*)&h02;
    }
}

// ---------------------------------------------------------------------------
// Kernel 2: B fragment table (fp16, scaled) — identical to R13/R14 (verified).
// ---------------------------------------------------------------------------
__global__ void bprep_kernel(const float* __restrict__ w) {
    int idx = blockIdx.x * 256 + threadIdx.x;      // < 147456
    if (idx >= 4 * NKC * 8 * 32) return;
    int lane = idx & 31;
    int qp   = (idx >> 5) & 7;
    int rest = idx >> 8;
    int kc   = rest % NKC;
    int nt   = rest / NKC;
    int g  = lane >> 2;
    int tg = lane & 3;
    const float s = 1.0f / 48.0f;

    unsigned r[4];
#pragma unroll
    for (int h = 0; h < 2; ++h) {
        int ni = 2 * qp + h;
        int n  = nt * 128 + ni * 8 + g;
        const float* wn_ = w + (size_t)n * KDIM;
        float b0x, b0y, b1x, b1y;
        if (kc < 128) {
            int c0 = 2 * kc, c1 = c0 + 1;
            int t0 = c_sigma[2 * tg], t1 = c_sigma[2 * tg + 1];
            b0x = wn_[c0 * 9 + t0] * s;  b0y = wn_[c0 * 9 + t1] * s;
            b1x = wn_[c1 * 9 + t0] * s;  b1y = wn_[c1 * 9 + t1] * s;
        } else {
            int tb = (kc - 128) * 16;
            b0x = wn_[(tb + 2 * tg)     * 9 + 8] * s;
            b0y = wn_[(tb + 2 * tg + 1) * 9 + 8] * s;
            b1x = wn_[(tb + 8 + 2 * tg)     * 9 + 8] * s;
            b1y = wn_[(tb + 8 + 2 * tg + 1) * 9 + 8] * s;
        }
        __half2 h0 = __halves2half2(__float2half_rn(b0x), __float2half_rn(b0y));
        __half2 h1 = __halves2half2(__float2half_rn(b1x), __float2half_rn(b1y));
        r[2 * h]     = *(unsigned*)&h0;
        r[2 * h + 1] = *(unsigned*)&h1;
    }
    g_Bq4[idx] = make_uint4(r[0], r[1], r[2], r[3]);
}

// ---------------------------------------------------------------------------
// Kernel 3: fp16 GEMM. CTA 128x128, 8 warps (4m x 2n), warp 32x64,
// 2 CTAs/SM (16 warps). A: 4 LDG.64 / warp-chunk, B: 4 LDG.128.
// ---------------------------------------------------------------------------
#define MMA_F16(acc, a, b0, b1)                                                \
    asm volatile(                                                              \
        "mma.sync.aligned.m16n8k16.row.col.f32.f16.f16.f32 "                   \
        "{%0,%1,%2,%3}, {%4,%5,%6,%7}, {%8,%9}, {%0,%1,%2,%3};\n"              \
        : "+f"((acc)[0]), "+f"((acc)[1]), "+f"((acc)[2]), "+f"((acc)[3])       \
        : "r"((a)[0]), "r"((a)[1]), "r"((a)[2]), "r"((a)[3]),                  \
          "r"(b0), "r"(b1))

__global__ void __launch_bounds__(256, 2)
gemm_kernel(const float* __restrict__ bias, float* __restrict__ out) {
    const int tid   = threadIdx.x;
    const int warp  = tid >> 5;
    const int lane  = tid & 31;
    const int g     = lane >> 2;
    const int tg    = lane & 3;
    const int warpm = warp & 3;
    const int wn    = warp >> 2;
    const int nt    = blockIdx.x;
    const int m0    = blockIdx.y << 7;

    // lane-constant plane + position offset (taps sigma[2tg], sigma[2tg+1])
    const uint2* pA = (tg == 1) ? g_P23v : (tg == 3) ? g_P02v : g_P01v;
    const int roff  = (tg == 2) ? XPW : (tg == 3) ? 1 : 0;

    int abase[2], tbase[2];
#pragma unroll
    for (int mi = 0; mi < 2; ++mi) {
        int m  = m0 + warpm * 32 + mi * 16 + g;
        int bb = (m >> 12) * IMGSTR + ((m >> 6) & 63) * XPW + (m & 63);
        abase[mi] = bb + roff;
        tbase[mi] = bb + XPW + 1;       // tap-8 position (y+1, x+1)
    }

    const uint4* Bt = g_Bq4 + (size_t)(nt * NKC) * 256 + wn * 128 + lane;

    float acc[2][8][4];
#pragma unroll
    for (int a = 0; a < 2; ++a)
#pragma unroll
        for (int b = 0; b < 8; ++b)
#pragma unroll
            for (int c = 0; c < 4; ++c) acc[a][b][c] = 0.f;

    unsigned aF[2][2][4];
    uint4    bF[2][4];

    // main chunk kc: uint2 entry cp=kc holds channels {2kc, 2kc+1} = k-cols
    // {0..7} and {8..15}; position +8 gives rows g+8 (a1/a3).
#define LOAD_MAIN(KC, S)                                                       \
    {                                                                          \
        const int co_ = (KC) * CPOS;                                           \
        _Pragma("unroll")                                                      \
        for (int mi = 0; mi < 2; ++mi) {                                       \
            uint2 u_ = pA[abase[mi] + co_];                                    \
            uint2 v_ = pA[abase[mi] + co_ + 8];                                \
            aF[S][mi][0] = u_.x;  aF[S][mi][2] = u_.y;                         \
            aF[S][mi][1] = v_.x;  aF[S][mi][3] = v_.y;                         \
        }                                                                      \
        const uint4* bp_ = Bt + (size_t)(KC) * 256;                            \
        _Pragma("unroll")                                                      \
        for (int np = 0; np < 4; ++np) bF[S][np] = bp_[np * 32];               \
    }

    // tail chunk T: tap-8 of channels tb..tb+15, tb = 16T; k-cols 2tg,2tg+1 =
    // channels tb+2tg, tb+2tg+1 -> low halves of uint2 cp = 8T+tg in P01 at
    // position (y+1, x+1); k-cols 8+2tg -> cp +4.
#define LOAD_TAIL(T, S)                                                        \
    {                                                                          \
        const int c0_ = ((T) * 8 + tg) * CPOS;                                 \
        const int c1_ = c0_ + 4 * CPOS;                                        \
        _Pragma("unroll")                                                      \
        for (int mi = 0; mi < 2; ++mi) {                                       \
            int b_ = tbase[mi];                                                \
            uint2 u_;                                                          \
            u_ = g_P01v[b_ + c0_];     aF[S][mi][0] = __byte_perm(u_.x, u_.y, 0x5410); \
            u_ = g_P01v[b_ + c0_ + 8]; aF[S][mi][1] = __byte_perm(u_.x, u_.y, 0x5410); \
            u_ = g_P01v[b_ + c1_];     aF[S][mi][2] = __byte_perm(u_.x, u_.y, 0x5410); \
            u_ = g_P01v[b_ + c1_ + 8]; aF[S][mi][3] = __byte_perm(u_.x, u_.y, 0x5410); \
        }                                                                      \
        const uint4* bp_ = Bt + (size_t)(128 + (T)) * 256;                     \
        _Pragma("unroll")                                                      \
        for (int np = 0; np < 4; ++np) bF[S][np] = bp_[np * 32];               \
    }

#define DO_MMAS(S)                                                             \
    _Pragma("unroll")                                                          \
    for (int np = 0; np < 4; ++np) {                                           \
        _Pragma("unroll")                                                      \
        for (int mi = 0; mi < 2; ++mi) {                                       \
            MMA_F16(acc[mi][2 * np],     aF[S][mi], bF[S][np].x, bF[S][np].y); \
            MMA_F16(acc[mi][2 * np + 1], aF[S][mi], bF[S][np].z, bF[S][np].w); \
        }                                                                      \
    }

    LOAD_MAIN(0, 0);

#pragma unroll 2
    for (int kc = 0; kc < 128; ++kc) {
        const int s = kc & 1;
        if (kc < 127) { LOAD_MAIN(kc + 1, s ^ 1); }
        else          { LOAD_TAIL(0, s ^ 1); }
        DO_MMAS(s);
    }
#pragma unroll 2
    for (int t = 0; t < 16; ++t) {
        const int s = (128 + t) & 1;
        if (t < 15) LOAD_TAIL(t + 1, s ^ 1);
        DO_MMAS(s);
    }
#undef LOAD_MAIN
#undef LOAD_TAIL
#undef DO_MMAS

    // epilogue: D[m][oc] -> out[n, oc, oh, ow] + bias
#pragma unroll
    for (int mi = 0; mi < 2; ++mi) {
        int m   = m0 + warpm * 32 + mi * 16 + g;
        int n16 = m >> 12;
        int rem = m & 4095;
#pragma unroll
        for (int ni = 0; ni < 8; ++ni) {
            int oc = nt * 128 + wn * 64 + ni * 8 + tg * 2;
            float bv0 = __ldg(&bias[oc]);
            float bv1 = __ldg(&bias[oc + 1]);
            float* p = out + (((size_t)(n16 * COUT + oc)) << 12) + rem;
            p[0]    = acc[mi][ni][0] + bv0;   // (m,   oc)
            p[4096] = acc[mi][ni][1] + bv1;   // (m,   oc+1)
            p[8]    = acc[mi][ni][2] + bv0;   // (m+8, oc)
            p[4104] = acc[mi][ni][3] + bv1;   // (m+8, oc+1)
        }
    }
}

// ---------------------------------------------------------------------------
extern "C" void kernel_launch(void* const* d_in, const int* in_sizes, int n_in,
                              void* d_out, int out_size) {
    const float* x    = (const float*)d_in[0];
    const float* w    = (const float*)d_in[1];
    const float* bias = (const float*)d_in[2];
    const float* bk   = (const float*)d_in[3];
    float* out = (float*)d_out;
    (void)in_sizes; (void)n_in; (void)out_size;

    prep_k_kernel<<<1, 32>>>(bk);

    blur_kernel<<<dim3(NIMG * CIN, 4), 256>>>(x);

    bprep_kernel<<<(4 * NKC * 8 * 32 + 255) / 256, 256>>>(w);

    dim3 grid(COUT / 128, MDIM / 128);      // (4, 512): n fast -> A L2 reuse
    gemm_kernel<<<grid, 256>>>(bias, out);
}